// round 8
// baseline (speedup 1.0000x reference)
#include <cuda_runtime.h>
#include <math.h>

#define NMAX 100000
#define ACC_W 16   // [coeff, edge_sca*coeff (6), edge_vec*coeff (9)]
#define EPB 256    // edges per block in edge kernel

__device__ __align__(16) float g_acc[NMAX * ACC_W];   // zero-initialized at load

// ---------------------------------------------------------------------------
// Edge phase (unchanged): staged coalesced loads + red.v4
// ---------------------------------------------------------------------------
__device__ __forceinline__ void red_v4(float* p, float a, float b, float c, float d) {
    asm volatile("red.global.add.v4.f32 [%0], {%1,%2,%3,%4};"
                 :: "l"(p), "f"(a), "f"(b), "f"(c), "f"(d) : "memory");
}

__global__ void __launch_bounds__(EPB)
edge_kernel(const float* __restrict__ edge_sca,
            const float* __restrict__ edge_vec,
            const float* __restrict__ gds,
            const int*   __restrict__ src_idx,
            int E) {
    __shared__ float s_sca[EPB * 6];
    __shared__ float s_vec[EPB * 9];

    int blockStart = blockIdx.x * EPB;
    int tid = threadIdx.x;
    int nEdges = min(EPB, E - blockStart);

    if (nEdges == EPB) {
        const float4* g4s = (const float4*)(edge_sca + (size_t)blockStart * 6);
        float4* s4s = (float4*)s_sca;
#pragma unroll 2
        for (int i = tid; i < (EPB * 6) / 4; i += EPB)
            s4s[i] = g4s[i];
        const float4* g4v = (const float4*)(edge_vec + (size_t)blockStart * 9);
        float4* s4v = (float4*)s_vec;
#pragma unroll 3
        for (int i = tid; i < (EPB * 9) / 4; i += EPB)
            s4v[i] = g4v[i];
    } else {
        for (int i = tid; i < nEdges * 6; i += EPB)
            s_sca[i] = edge_sca[(size_t)blockStart * 6 + i];
        for (int i = tid; i < nEdges * 9; i += EPB)
            s_vec[i] = edge_vec[(size_t)blockStart * 9 + i];
    }
    __syncthreads();

    if (tid >= nEdges) return;
    int e = blockStart + tid;

    float dist = __ldg(gds + e);
    if (dist > 10.0f || dist < 0.0f) return;
    float coeff = 0.5f * (__cosf(dist * 0.31415926535f) + 1.0f);

    int src = __ldg(src_idx + e);

    float es[6];
#pragma unroll
    for (int c = 0; c < 6; c++) es[c] = s_sca[tid * 6 + c] * coeff;
    float ev[9];
#pragma unroll
    for (int c = 0; c < 9; c++) ev[c] = s_vec[tid * 9 + c] * coeff;

    float* base = g_acc + (size_t)src * ACC_W;
    red_v4(base + 0,  coeff, es[0], es[1], es[2]);
    red_v4(base + 4,  es[3], es[4], es[5], ev[0]);
    red_v4(base + 8,  ev[1], ev[2], ev[3], ev[4]);
    red_v4(base + 12, ev[5], ev[6], ev[7], ev[8]);
}

// ---------------------------------------------------------------------------
// Node phase: 4 lanes per node, 128-bit smem traffic, occupancy-capped regs.
// ---------------------------------------------------------------------------
#define O_NSS   0      // 4x16
#define O_BNSS  64     // 16
#define O_ESS   80     // 6x16
#define O_BESS  176    // 16
#define O_NSV   192    // 4x16
#define O_BNSV  256    // 16
#define O_ESV   272    // 6x16
#define O_BESV  368    // 16
#define O_NVV   384    // 3x16
#define O_EVV   432    // 3x16
#define O_LV    480    // 16x16
#define O_LV2   736    // 16x16
#define O_LS    992    // 32x16
#define O_GATE  1504   // 16x16
#define O_BGATE 1760   // 16
#define O_DIR   1776   // 16x16
#define SW_TOT  2032

#define NPB 64         // nodes per block
#define TPB 256        // threads per block (4 per node)
#define BUF_W 68       // 64 payload + 4 pad floats

__global__ void __launch_bounds__(TPB, 4)
node_kernel(const float* __restrict__ node_sca,
            const float* __restrict__ node_vec,
            const float* __restrict__ W_nss, const float* __restrict__ b_nss,
            const float* __restrict__ W_ess, const float* __restrict__ b_ess,
            const float* __restrict__ W_nsv, const float* __restrict__ b_nsv,
            const float* __restrict__ W_esv, const float* __restrict__ b_esv,
            const float* __restrict__ W_nvv, const float* __restrict__ W_evv,
            const float* __restrict__ W_lv,  const float* __restrict__ W_lv2,
            const float* __restrict__ W_ls,  const float* __restrict__ W_gate,
            const float* __restrict__ b_gate,const float* __restrict__ W_dir,
            float* __restrict__ out, int N) {
    __shared__ __align__(16) float sW[SW_TOT];
    __shared__ float s_nv[NPB * 9];
    __shared__ __align__(16) float bufA[NPB][BUF_W];  // aggr -> osca -> ovec
    __shared__ __align__(16) float bufB[NPB][BUF_W];  // v_inter + v_norm

    int tid = threadIdx.x;
    int nd  = tid >> 2;          // node within block
    int j   = tid & 3;           // sub-lane: owns output channels o0..o0+3
    int o0  = j * 4;
    int blockStart = blockIdx.x * NPB;
    int nNodes = min(NPB, N - blockStart);
    int n = blockStart + nd;
    bool active = (nd < nNodes);

    {   // weights -> shared
        const float* srcs[16] = {W_nss, b_nss, W_ess, b_ess, W_nsv, b_nsv,
                                 W_esv, b_esv, W_nvv, W_evv, W_lv, W_lv2,
                                 W_ls, W_gate, b_gate, W_dir};
        const int offs[17] = {O_NSS, O_BNSS, O_ESS, O_BESS, O_NSV, O_BNSV,
                              O_ESV, O_BESV, O_NVV, O_EVV, O_LV, O_LV2,
                              O_LS, O_GATE, O_BGATE, O_DIR, SW_TOT};
        for (int a = 0; a < 16; a++) {
            int cnt = offs[a + 1] - offs[a];
            for (int i = tid; i < cnt; i += TPB)
                sW[offs[a] + i] = srcs[a][i];
        }
    }
    {   // node_vec -> shared (coalesced)
        for (int i = tid; i < nNodes * 9; i += TPB)
            s_nv[i] = node_vec[(size_t)blockStart * 9 + i];
    }
    __syncthreads();

    // ---- per-node inputs ----
    float ns[4] = {0, 0, 0, 0};
    float nv[9] = {0};
    float accv[16] = {0};
    if (active) {
        float4 ns4 = ((const float4*)node_sca)[n];
        ns[0] = ns4.x; ns[1] = ns4.y; ns[2] = ns4.z; ns[3] = ns4.w;
#pragma unroll
        for (int i = 0; i < 9; i++) nv[i] = s_nv[nd * 9 + i];
        const float4* a4 = (const float4*)(g_acc + (size_t)n * ACC_W);
#pragma unroll
        for (int q = 0; q < 4; q++) {
            float4 v = a4[q];
            accv[q * 4 + 0] = v.x; accv[q * 4 + 1] = v.y;
            accv[q * 4 + 2] = v.z; accv[q * 4 + 3] = v.w;
        }
    }
    __syncwarp();
    if (active)   // zero quarter j for next graph replay
        ((float4*)(g_acc + (size_t)n * ACC_W))[j] = make_float4(0.f, 0.f, 0.f, 0.f);

    float Cs = accv[0];
    float* Es = accv + 1;
    float* Ev = accv + 7;      // 3x3 row-major [k*3+i]

    // ---- Phase 1: aggr channels c in {4j..4j+3}; STS.128 per channel ----
    if (active) {
#pragma unroll
        for (int cc = 0; cc < 4; cc++) {
            int c = o0 + cc;
            float nss = sW[O_BNSS + c];
            float nsv = sW[O_BNSV + c];
#pragma unroll
            for (int k = 0; k < 4; k++) {
                nss += ns[k] * sW[O_NSS + k * 16 + c];
                nsv += ns[k] * sW[O_NSV + k * 16 + c];
            }
            float ess = sW[O_BESS + c] * Cs;
            float esv = sW[O_BESV + c] * Cs;
#pragma unroll
            for (int k = 0; k < 6; k++) {
                ess += Es[k] * sW[O_ESS + k * 16 + c];
                esv += Es[k] * sW[O_ESV + k * 16 + c];
            }
            float av[3];
#pragma unroll
            for (int i = 0; i < 3; i++) {
                float nvv = 0.f, evv = 0.f;
#pragma unroll
                for (int k = 0; k < 3; k++) {
                    nvv += nv[k * 3 + i] * sW[O_NVV + k * 16 + c];
                    evv += Ev[k * 3 + i] * sW[O_EVV + k * 16 + c];
                }
                av[i] = nvv * esv + nsv * evv;
            }
            *(float4*)&bufA[nd][c * 4] = make_float4(av[0], av[1], av[2], nss * ess);
        }
    }
    __syncwarp();

    // ---- Phase 2: lv + ls-scalar-half ----
    float vi[4][3];
    float osca[4];
#pragma unroll
    for (int oo = 0; oo < 4; oo++) {
        vi[oo][0] = 0.f; vi[oo][1] = 0.f; vi[oo][2] = 0.f; osca[oo] = 0.f;
    }
    if (active) {
#pragma unroll
        for (int c = 0; c < 16; c++) {
            float4 a   = *(const float4*)&bufA[nd][c * 4];
            float4 wlv = *(const float4*)&sW[O_LV + c * 16 + o0];
            float4 wls = *(const float4*)&sW[O_LS + (c + 16) * 16 + o0];
            vi[0][0] += a.x * wlv.x; vi[0][1] += a.y * wlv.x; vi[0][2] += a.z * wlv.x;
            vi[1][0] += a.x * wlv.y; vi[1][1] += a.y * wlv.y; vi[1][2] += a.z * wlv.y;
            vi[2][0] += a.x * wlv.z; vi[2][1] += a.y * wlv.z; vi[2][2] += a.z * wlv.z;
            vi[3][0] += a.x * wlv.w; vi[3][1] += a.y * wlv.w; vi[3][2] += a.z * wlv.w;
            osca[0] += a.w * wls.x; osca[1] += a.w * wls.y;
            osca[2] += a.w * wls.z; osca[3] += a.w * wls.w;
        }
#pragma unroll
        for (int oo = 0; oo < 4; oo++) {
            float vn = sqrtf(vi[oo][0] * vi[oo][0] + vi[oo][1] * vi[oo][1] +
                             vi[oo][2] * vi[oo][2]);
            *(float4*)&bufB[nd][(o0 + oo) * 4] =
                make_float4(vi[oo][0], vi[oo][1], vi[oo][2], vn);
        }
    }
    __syncwarp();

    // ---- Phase 3: osca v_norm-half; publish osca ----
    if (active) {
#pragma unroll
        for (int c = 0; c < 16; c++) {
            float vn = bufB[nd][c * 4 + 3];
            float4 wls = *(const float4*)&sW[O_LS + c * 16 + o0];
            osca[0] += vn * wls.x; osca[1] += vn * wls.y;
            osca[2] += vn * wls.z; osca[3] += vn * wls.w;
        }
        *(float4*)&bufA[nd][o0] = make_float4(osca[0], osca[1], osca[2], osca[3]);
    }
    __syncwarp();

    // ---- Phase 4: gate ----
    float gate[4] = {sW[O_BGATE + o0], sW[O_BGATE + o0 + 1],
                     sW[O_BGATE + o0 + 2], sW[O_BGATE + o0 + 3]};
    if (active) {
#pragma unroll
        for (int c4 = 0; c4 < 4; c4++) {
            float4 oc = *(const float4*)&bufA[nd][c4 * 4];
            float ocv[4] = {oc.x, oc.y, oc.z, oc.w};
#pragma unroll
            for (int q = 0; q < 4; q++) {
                float4 wg = *(const float4*)&sW[O_GATE + (c4 * 4 + q) * 16 + o0];
                gate[0] += ocv[q] * wg.x; gate[1] += ocv[q] * wg.y;
                gate[2] += ocv[q] * wg.z; gate[3] += ocv[q] * wg.w;
            }
        }
    }
#pragma unroll
    for (int oo = 0; oo < 4; oo++) gate[oo] = 1.0f / (1.0f + __expf(-gate[oo]));
    __syncwarp();   // osca reads done; bufA reusable for ovec

    // ---- Phase 5: lv2 -> ovec (gated); publish ----
    float ov[4][3];
#pragma unroll
    for (int oo = 0; oo < 4; oo++) { ov[oo][0] = 0.f; ov[oo][1] = 0.f; ov[oo][2] = 0.f; }
    if (active) {
#pragma unroll
        for (int c = 0; c < 16; c++) {
            float4 v = *(const float4*)&bufB[nd][c * 4];   // vi0,vi1,vi2,norm
            float4 w = *(const float4*)&sW[O_LV2 + c * 16 + o0];
            ov[0][0] += v.x * w.x; ov[0][1] += v.y * w.x; ov[0][2] += v.z * w.x;
            ov[1][0] += v.x * w.y; ov[1][1] += v.y * w.y; ov[1][2] += v.z * w.y;
            ov[2][0] += v.x * w.z; ov[2][1] += v.y * w.z; ov[2][2] += v.z * w.z;
            ov[3][0] += v.x * w.w; ov[3][1] += v.y * w.w; ov[3][2] += v.z * w.w;
        }
#pragma unroll
        for (int oo = 0; oo < 4; oo++) {
            ov[oo][0] *= gate[oo]; ov[oo][1] *= gate[oo]; ov[oo][2] *= gate[oo];
            *(float4*)&bufA[nd][(o0 + oo) * 4] =
                make_float4(ov[oo][0], ov[oo][1], ov[oo][2], 0.f);
        }
    }
    __syncwarp();

    // ---- Phase 6: direction + VNLeakyReLU + writes ----
    if (!active) return;
    float d[4][3];
#pragma unroll
    for (int oo = 0; oo < 4; oo++) { d[oo][0] = 0.f; d[oo][1] = 0.f; d[oo][2] = 0.f; }
#pragma unroll
    for (int c = 0; c < 16; c++) {
        float4 v = *(const float4*)&bufA[nd][c * 4];
        float4 w = *(const float4*)&sW[O_DIR + c * 16 + o0];
        d[0][0] += v.x * w.x; d[0][1] += v.y * w.x; d[0][2] += v.z * w.x;
        d[1][0] += v.x * w.y; d[1][1] += v.y * w.y; d[1][2] += v.z * w.y;
        d[2][0] += v.x * w.z; d[2][1] += v.y * w.z; d[2][2] += v.z * w.z;
        d[3][0] += v.x * w.w; d[3][1] += v.y * w.w; d[3][2] += v.z * w.w;
    }

    float res[12];
#pragma unroll
    for (int oo = 0; oo < 4; oo++) {
        float v0 = ov[oo][0], v1 = ov[oo][1], v2 = ov[oo][2];
        float d0 = d[oo][0], d1 = d[oo][1], d2 = d[oo][2];
        float dot = v0 * d0 + v1 * d1 + v2 * d2;
        float r0 = v0, r1 = v1, r2 = v2;
        if (dot < 0.0f) {
            float k = 0.8f * dot / (d0 * d0 + d1 * d1 + d2 * d2 + 1e-6f);
            r0 = v0 - k * d0; r1 = v1 - k * d1; r2 = v2 - k * d2;
        }
        res[oo * 3 + 0] = r0; res[oo * 3 + 1] = r1; res[oo * 3 + 2] = r2;
    }

    float* out_vec = out + (size_t)N * 16;
    float4* dv = (float4*)(out_vec + (size_t)n * 48 + j * 12);
#pragma unroll
    for (int q = 0; q < 3; q++)
        dv[q] = make_float4(res[q * 4 + 0], res[q * 4 + 1],
                            res[q * 4 + 2], res[q * 4 + 3]);

    float s0 = osca[0], s1 = osca[1], s2 = osca[2], s3 = osca[3];
    s0 = (s0 >= 0.f) ? s0 : 0.01f * s0;
    s1 = (s1 >= 0.f) ? s1 : 0.01f * s1;
    s2 = (s2 >= 0.f) ? s2 : 0.01f * s2;
    s3 = (s3 >= 0.f) ? s3 : 0.01f * s3;
    ((float4*)(out + (size_t)n * 16 + o0))[0] = make_float4(s0, s1, s2, s3);
}

// ---------------------------------------------------------------------------
extern "C" void kernel_launch(void* const* d_in, const int* in_sizes, int n_in,
                              void* d_out, int out_size) {
    const float* node_sca = (const float*)d_in[0];
    const float* node_vec = (const float*)d_in[1];
    const float* edge_sca = (const float*)d_in[2];
    const float* edge_vec = (const float*)d_in[3];
    const float* gds      = (const float*)d_in[4];
    const int*   ei       = (const int*)d_in[5];   // [2,E]; row 0 = src
    const float* W_nss  = (const float*)d_in[6];
    const float* b_nss  = (const float*)d_in[7];
    const float* W_ess  = (const float*)d_in[8];
    const float* b_ess  = (const float*)d_in[9];
    const float* W_nsv  = (const float*)d_in[10];
    const float* b_nsv  = (const float*)d_in[11];
    const float* W_esv  = (const float*)d_in[12];
    const float* b_esv  = (const float*)d_in[13];
    const float* W_nvv  = (const float*)d_in[14];
    const float* W_evv  = (const float*)d_in[15];
    const float* W_lv   = (const float*)d_in[16];
    const float* W_lv2  = (const float*)d_in[17];
    const float* W_ls   = (const float*)d_in[18];
    const float* W_gate = (const float*)d_in[19];
    const float* b_gate = (const float*)d_in[20];
    const float* W_dir  = (const float*)d_in[21];

    int N = in_sizes[0] / 4;
    int E = in_sizes[4];

    int eblocks = (E + EPB - 1) / EPB;
    edge_kernel<<<eblocks, EPB>>>(edge_sca, edge_vec, gds, ei, E);

    int nblocks = (N + NPB - 1) / NPB;
    node_kernel<<<nblocks, TPB>>>(node_sca, node_vec,
                                  W_nss, b_nss, W_ess, b_ess,
                                  W_nsv, b_nsv, W_esv, b_esv,
                                  W_nvv, W_evv, W_lv, W_lv2,
                                  W_ls, W_gate, b_gate, W_dir,
                                  (float*)d_out, N);
}

// round 9
// speedup vs baseline: 1.1017x; 1.1017x over previous
#include <cuda_runtime.h>
#include <math.h>

#define NMAX 100000
#define ACC_W 16   // [coeff, edge_sca*coeff (6), edge_vec*coeff (9)]
#define EPB 256    // edges per block in edge kernel

__device__ __align__(16) float g_acc[NMAX * ACC_W];   // zero-initialized at load

// ---------------------------------------------------------------------------
// Edge phase (unchanged): staged coalesced loads + red.v4
// ---------------------------------------------------------------------------
__device__ __forceinline__ void red_v4(float* p, float a, float b, float c, float d) {
    asm volatile("red.global.add.v4.f32 [%0], {%1,%2,%3,%4};"
                 :: "l"(p), "f"(a), "f"(b), "f"(c), "f"(d) : "memory");
}

__global__ void __launch_bounds__(EPB)
edge_kernel(const float* __restrict__ edge_sca,
            const float* __restrict__ edge_vec,
            const float* __restrict__ gds,
            const int*   __restrict__ src_idx,
            int E) {
    __shared__ float s_sca[EPB * 6];
    __shared__ float s_vec[EPB * 9];

    int blockStart = blockIdx.x * EPB;
    int tid = threadIdx.x;
    int nEdges = min(EPB, E - blockStart);

    if (nEdges == EPB) {
        const float4* g4s = (const float4*)(edge_sca + (size_t)blockStart * 6);
        float4* s4s = (float4*)s_sca;
#pragma unroll 2
        for (int i = tid; i < (EPB * 6) / 4; i += EPB)
            s4s[i] = g4s[i];
        const float4* g4v = (const float4*)(edge_vec + (size_t)blockStart * 9);
        float4* s4v = (float4*)s_vec;
#pragma unroll 3
        for (int i = tid; i < (EPB * 9) / 4; i += EPB)
            s4v[i] = g4v[i];
    } else {
        for (int i = tid; i < nEdges * 6; i += EPB)
            s_sca[i] = edge_sca[(size_t)blockStart * 6 + i];
        for (int i = tid; i < nEdges * 9; i += EPB)
            s_vec[i] = edge_vec[(size_t)blockStart * 9 + i];
    }
    __syncthreads();

    if (tid >= nEdges) return;
    int e = blockStart + tid;

    float dist = __ldg(gds + e);
    if (dist > 10.0f || dist < 0.0f) return;
    float coeff = 0.5f * (__cosf(dist * 0.31415926535f) + 1.0f);

    int src = __ldg(src_idx + e);

    float es[6];
#pragma unroll
    for (int c = 0; c < 6; c++) es[c] = s_sca[tid * 6 + c] * coeff;
    float ev[9];
#pragma unroll
    for (int c = 0; c < 9; c++) ev[c] = s_vec[tid * 9 + c] * coeff;

    float* base = g_acc + (size_t)src * ACC_W;
    red_v4(base + 0,  coeff, es[0], es[1], es[2]);
    red_v4(base + 4,  es[3], es[4], es[5], ev[0]);
    red_v4(base + 8,  ev[1], ev[2], ev[3], ev[4]);
    red_v4(base + 12, ev[5], ev[6], ev[7], ev[8]);
}

// ---------------------------------------------------------------------------
// Node phase: 4 lanes per node, all smem traffic 128-bit (incl. transposed
// phase-1 projection weights). No occupancy cap (R8 showed it forces spills).
// ---------------------------------------------------------------------------
// sW layout (floats, all float4-aligned)
#define O_BNSS  0      // 16
#define O_BNSV  16     // 16
#define O_BGATE 32     // 16
#define O_LV    48     // 16x16
#define O_LV2   304    // 16x16
#define O_LS    560    // 32x16
#define O_GATE  1072   // 16x16
#define O_DIR   1328   // 16x16
#define T_NSS   1584   // 16x4  [c][k]
#define T_NSV   1648   // 16x4
#define T_NVV   1712   // 16x4  (k<3 data, k=3 zero)
#define T_EVV   1776   // 16x4
#define T_ESS   1840   // 16x8  (k<6 data, k=6 bias, k=7 zero)
#define T_ESV   1968   // 16x8
#define SW_TOT  2096

#define NPB 64         // nodes per block
#define TPB 256        // threads per block (4 per node)
#define BUF_W 68       // 64 payload + 4 pad floats

__global__ void __launch_bounds__(TPB)
node_kernel(const float* __restrict__ node_sca,
            const float* __restrict__ node_vec,
            const float* __restrict__ W_nss, const float* __restrict__ b_nss,
            const float* __restrict__ W_ess, const float* __restrict__ b_ess,
            const float* __restrict__ W_nsv, const float* __restrict__ b_nsv,
            const float* __restrict__ W_esv, const float* __restrict__ b_esv,
            const float* __restrict__ W_nvv, const float* __restrict__ W_evv,
            const float* __restrict__ W_lv,  const float* __restrict__ W_lv2,
            const float* __restrict__ W_ls,  const float* __restrict__ W_gate,
            const float* __restrict__ b_gate,const float* __restrict__ W_dir,
            float* __restrict__ out, int N) {
    __shared__ __align__(16) float sW[SW_TOT];
    __shared__ float s_nv[NPB * 9];
    __shared__ __align__(16) float bufA[NPB][BUF_W];  // aggr -> osca -> ovec
    __shared__ __align__(16) float bufB[NPB][BUF_W];  // v_inter + v_norm

    int tid = threadIdx.x;
    int nd  = tid >> 2;          // node within block
    int j   = tid & 3;           // sub-lane: owns output channels o0..o0+3
    int o0  = j * 4;
    int blockStart = blockIdx.x * NPB;
    int nNodes = min(NPB, N - blockStart);
    int n = blockStart + nd;
    bool active = (nd < nNodes);

    {   // big weights -> shared (direct layout)
        for (int i = tid; i < 16; i += TPB) {
            sW[O_BNSS + i]  = b_nss[i];
            sW[O_BNSV + i]  = b_nsv[i];
            sW[O_BGATE + i] = b_gate[i];
        }
        for (int i = tid; i < 256; i += TPB) {
            sW[O_LV + i]   = W_lv[i];
            sW[O_LV2 + i]  = W_lv2[i];
            sW[O_GATE + i] = W_gate[i];
            sW[O_DIR + i]  = W_dir[i];
        }
        for (int i = tid; i < 512; i += TPB)
            sW[O_LS + i] = W_ls[i];
        // transposed phase-1 weights: [c][k]
        for (int i = tid; i < 64; i += TPB) {
            int c = i >> 2, k = i & 3;
            sW[T_NSS + i] = W_nss[k * 16 + c];
            sW[T_NSV + i] = W_nsv[k * 16 + c];
            sW[T_NVV + i] = (k < 3) ? W_nvv[k * 16 + c] : 0.f;
            sW[T_EVV + i] = (k < 3) ? W_evv[k * 16 + c] : 0.f;
        }
        for (int i = tid; i < 128; i += TPB) {
            int c = i >> 3, k = i & 7;
            sW[T_ESS + i] = (k < 6) ? W_ess[k * 16 + c] : ((k == 6) ? b_ess[c] : 0.f);
            sW[T_ESV + i] = (k < 6) ? W_esv[k * 16 + c] : ((k == 6) ? b_esv[c] : 0.f);
        }
    }
    {   // node_vec -> shared (coalesced)
        for (int i = tid; i < nNodes * 9; i += TPB)
            s_nv[i] = node_vec[(size_t)blockStart * 9 + i];
    }
    __syncthreads();

    // ---- per-node inputs ----
    float ns[4] = {0, 0, 0, 0};
    float nv[9] = {0};
    float accv[16] = {0};
    if (active) {
        float4 ns4 = ((const float4*)node_sca)[n];
        ns[0] = ns4.x; ns[1] = ns4.y; ns[2] = ns4.z; ns[3] = ns4.w;
#pragma unroll
        for (int i = 0; i < 9; i++) nv[i] = s_nv[nd * 9 + i];
        const float4* a4 = (const float4*)(g_acc + (size_t)n * ACC_W);
#pragma unroll
        for (int q = 0; q < 4; q++) {
            float4 v = a4[q];
            accv[q * 4 + 0] = v.x; accv[q * 4 + 1] = v.y;
            accv[q * 4 + 2] = v.z; accv[q * 4 + 3] = v.w;
        }
    }
    __syncwarp();
    if (active)   // zero quarter j for next graph replay
        ((float4*)(g_acc + (size_t)n * ACC_W))[j] = make_float4(0.f, 0.f, 0.f, 0.f);

    float Cs = accv[0];
    float* Es = accv + 1;
    float* Ev = accv + 7;      // 3x3 row-major [k*3+i]

    // ---- Phase 1: aggr channels c in {4j..4j+3}; vectorized weight loads ----
    if (active) {
#pragma unroll
        for (int cc = 0; cc < 4; cc++) {
            int c = o0 + cc;
            float4 wn = *(const float4*)&sW[T_NSS + c * 4];
            float nss = sW[O_BNSS + c] + ns[0] * wn.x + ns[1] * wn.y
                                       + ns[2] * wn.z + ns[3] * wn.w;
            float4 wv = *(const float4*)&sW[T_NSV + c * 4];
            float nsv = sW[O_BNSV + c] + ns[0] * wv.x + ns[1] * wv.y
                                       + ns[2] * wv.z + ns[3] * wv.w;
            float4 e0 = *(const float4*)&sW[T_ESS + c * 8];
            float4 e1 = *(const float4*)&sW[T_ESS + c * 8 + 4];
            float ess = Es[0] * e0.x + Es[1] * e0.y + Es[2] * e0.z + Es[3] * e0.w
                      + Es[4] * e1.x + Es[5] * e1.y + Cs * e1.z;   // e1.z = bias
            float4 f0 = *(const float4*)&sW[T_ESV + c * 8];
            float4 f1 = *(const float4*)&sW[T_ESV + c * 8 + 4];
            float esv = Es[0] * f0.x + Es[1] * f0.y + Es[2] * f0.z + Es[3] * f0.w
                      + Es[4] * f1.x + Es[5] * f1.y + Cs * f1.z;
            float4 wnv = *(const float4*)&sW[T_NVV + c * 4];
            float4 wev = *(const float4*)&sW[T_EVV + c * 4];
            float av[3];
#pragma unroll
            for (int i = 0; i < 3; i++) {
                float nvv = nv[i] * wnv.x + nv[3 + i] * wnv.y + nv[6 + i] * wnv.z;
                float evv = Ev[i] * wev.x + Ev[3 + i] * wev.y + Ev[6 + i] * wev.z;
                av[i] = nvv * esv + nsv * evv;
            }
            *(float4*)&bufA[nd][c * 4] = make_float4(av[0], av[1], av[2], nss * ess);
        }
    }
    __syncwarp();

    // ---- Phase 2: lv + ls-scalar-half ----
    float vi[4][3];
    float osca[4];
#pragma unroll
    for (int oo = 0; oo < 4; oo++) {
        vi[oo][0] = 0.f; vi[oo][1] = 0.f; vi[oo][2] = 0.f; osca[oo] = 0.f;
    }
    if (active) {
#pragma unroll
        for (int c = 0; c < 16; c++) {
            float4 a   = *(const float4*)&bufA[nd][c * 4];
            float4 wlv = *(const float4*)&sW[O_LV + c * 16 + o0];
            float4 wls = *(const float4*)&sW[O_LS + (c + 16) * 16 + o0];
            vi[0][0] += a.x * wlv.x; vi[0][1] += a.y * wlv.x; vi[0][2] += a.z * wlv.x;
            vi[1][0] += a.x * wlv.y; vi[1][1] += a.y * wlv.y; vi[1][2] += a.z * wlv.y;
            vi[2][0] += a.x * wlv.z; vi[2][1] += a.y * wlv.z; vi[2][2] += a.z * wlv.z;
            vi[3][0] += a.x * wlv.w; vi[3][1] += a.y * wlv.w; vi[3][2] += a.z * wlv.w;
            osca[0] += a.w * wls.x; osca[1] += a.w * wls.y;
            osca[2] += a.w * wls.z; osca[3] += a.w * wls.w;
        }
#pragma unroll
        for (int oo = 0; oo < 4; oo++) {
            float vn = sqrtf(vi[oo][0] * vi[oo][0] + vi[oo][1] * vi[oo][1] +
                             vi[oo][2] * vi[oo][2]);
            *(float4*)&bufB[nd][(o0 + oo) * 4] =
                make_float4(vi[oo][0], vi[oo][1], vi[oo][2], vn);
        }
    }
    __syncwarp();

    // ---- Phase 3: osca v_norm-half; publish osca ----
    if (active) {
#pragma unroll
        for (int c = 0; c < 16; c++) {
            float vn = bufB[nd][c * 4 + 3];
            float4 wls = *(const float4*)&sW[O_LS + c * 16 + o0];
            osca[0] += vn * wls.x; osca[1] += vn * wls.y;
            osca[2] += vn * wls.z; osca[3] += vn * wls.w;
        }
        *(float4*)&bufA[nd][o0] = make_float4(osca[0], osca[1], osca[2], osca[3]);
    }
    __syncwarp();

    // ---- Phase 4: gate ----
    float gate[4] = {sW[O_BGATE + o0], sW[O_BGATE + o0 + 1],
                     sW[O_BGATE + o0 + 2], sW[O_BGATE + o0 + 3]};
    if (active) {
#pragma unroll
        for (int c4 = 0; c4 < 4; c4++) {
            float4 oc = *(const float4*)&bufA[nd][c4 * 4];
            float ocv[4] = {oc.x, oc.y, oc.z, oc.w};
#pragma unroll
            for (int q = 0; q < 4; q++) {
                float4 wg = *(const float4*)&sW[O_GATE + (c4 * 4 + q) * 16 + o0];
                gate[0] += ocv[q] * wg.x; gate[1] += ocv[q] * wg.y;
                gate[2] += ocv[q] * wg.z; gate[3] += ocv[q] * wg.w;
            }
        }
    }
#pragma unroll
    for (int oo = 0; oo < 4; oo++) gate[oo] = 1.0f / (1.0f + __expf(-gate[oo]));
    __syncwarp();   // osca reads done; bufA reusable for ovec

    // ---- Phase 5: lv2 -> ovec (gated); publish ----
    float ov[4][3];
#pragma unroll
    for (int oo = 0; oo < 4; oo++) { ov[oo][0] = 0.f; ov[oo][1] = 0.f; ov[oo][2] = 0.f; }
    if (active) {
#pragma unroll
        for (int c = 0; c < 16; c++) {
            float4 v = *(const float4*)&bufB[nd][c * 4];   // vi0,vi1,vi2,norm
            float4 w = *(const float4*)&sW[O_LV2 + c * 16 + o0];
            ov[0][0] += v.x * w.x; ov[0][1] += v.y * w.x; ov[0][2] += v.z * w.x;
            ov[1][0] += v.x * w.y; ov[1][1] += v.y * w.y; ov[1][2] += v.z * w.y;
            ov[2][0] += v.x * w.z; ov[2][1] += v.y * w.z; ov[2][2] += v.z * w.z;
            ov[3][0] += v.x * w.w; ov[3][1] += v.y * w.w; ov[3][2] += v.z * w.w;
        }
#pragma unroll
        for (int oo = 0; oo < 4; oo++) {
            ov[oo][0] *= gate[oo]; ov[oo][1] *= gate[oo]; ov[oo][2] *= gate[oo];
            *(float4*)&bufA[nd][(o0 + oo) * 4] =
                make_float4(ov[oo][0], ov[oo][1], ov[oo][2], 0.f);
        }
    }
    __syncwarp();

    // ---- Phase 6: direction + VNLeakyReLU + writes ----
    if (!active) return;
    float d[4][3];
#pragma unroll
    for (int oo = 0; oo < 4; oo++) { d[oo][0] = 0.f; d[oo][1] = 0.f; d[oo][2] = 0.f; }
#pragma unroll
    for (int c = 0; c < 16; c++) {
        float4 v = *(const float4*)&bufA[nd][c * 4];
        float4 w = *(const float4*)&sW[O_DIR + c * 16 + o0];
        d[0][0] += v.x * w.x; d[0][1] += v.y * w.x; d[0][2] += v.z * w.x;
        d[1][0] += v.x * w.y; d[1][1] += v.y * w.y; d[1][2] += v.z * w.y;
        d[2][0] += v.x * w.z; d[2][1] += v.y * w.z; d[2][2] += v.z * w.z;
        d[3][0] += v.x * w.w; d[3][1] += v.y * w.w; d[3][2] += v.z * w.w;
    }

    float res[12];
#pragma unroll
    for (int oo = 0; oo < 4; oo++) {
        float v0 = ov[oo][0], v1 = ov[oo][1], v2 = ov[oo][2];
        float d0 = d[oo][0], d1 = d[oo][1], d2 = d[oo][2];
        float dot = v0 * d0 + v1 * d1 + v2 * d2;
        float r0 = v0, r1 = v1, r2 = v2;
        if (dot < 0.0f) {
            float k = 0.8f * dot / (d0 * d0 + d1 * d1 + d2 * d2 + 1e-6f);
            r0 = v0 - k * d0; r1 = v1 - k * d1; r2 = v2 - k * d2;
        }
        res[oo * 3 + 0] = r0; res[oo * 3 + 1] = r1; res[oo * 3 + 2] = r2;
    }

    float* out_vec = out + (size_t)N * 16;
    float4* dv = (float4*)(out_vec + (size_t)n * 48 + j * 12);
#pragma unroll
    for (int q = 0; q < 3; q++)
        dv[q] = make_float4(res[q * 4 + 0], res[q * 4 + 1],
                            res[q * 4 + 2], res[q * 4 + 3]);

    float s0 = osca[0], s1 = osca[1], s2 = osca[2], s3 = osca[3];
    s0 = (s0 >= 0.f) ? s0 : 0.01f * s0;
    s1 = (s1 >= 0.f) ? s1 : 0.01f * s1;
    s2 = (s2 >= 0.f) ? s2 : 0.01f * s2;
    s3 = (s3 >= 0.f) ? s3 : 0.01f * s3;
    ((float4*)(out + (size_t)n * 16 + o0))[0] = make_float4(s0, s1, s2, s3);
}

// ---------------------------------------------------------------------------
extern "C" void kernel_launch(void* const* d_in, const int* in_sizes, int n_in,
                              void* d_out, int out_size) {
    const float* node_sca = (const float*)d_in[0];
    const float* node_vec = (const float*)d_in[1];
    const float* edge_sca = (const float*)d_in[2];
    const float* edge_vec = (const float*)d_in[3];
    const float* gds      = (const float*)d_in[4];
    const int*   ei       = (const int*)d_in[5];   // [2,E]; row 0 = src
    const float* W_nss  = (const float*)d_in[6];
    const float* b_nss  = (const float*)d_in[7];
    const float* W_ess  = (const float*)d_in[8];
    const float* b_ess  = (const float*)d_in[9];
    const float* W_nsv  = (const float*)d_in[10];
    const float* b_nsv  = (const float*)d_in[11];
    const float* W_esv  = (const float*)d_in[12];
    const float* b_esv  = (const float*)d_in[13];
    const float* W_nvv  = (const float*)d_in[14];
    const float* W_evv  = (const float*)d_in[15];
    const float* W_lv   = (const float*)d_in[16];
    const float* W_lv2  = (const float*)d_in[17];
    const float* W_ls   = (const float*)d_in[18];
    const float* W_gate = (const float*)d_in[19];
    const float* b_gate = (const float*)d_in[20];
    const float* W_dir  = (const float*)d_in[21];

    int N = in_sizes[0] / 4;
    int E = in_sizes[4];

    int eblocks = (E + EPB - 1) / EPB;
    edge_kernel<<<eblocks, EPB>>>(edge_sca, edge_vec, gds, ei, E);

    int nblocks = (N + NPB - 1) / NPB;
    node_kernel<<<nblocks, TPB>>>(node_sca, node_vec,
                                  W_nss, b_nss, W_ess, b_ess,
                                  W_nsv, b_nsv, W_esv, b_esv,
                                  W_nvv, W_evv, W_lv, W_lv2,
                                  W_ls, W_gate, b_gate, W_dir,
                                  (float*)d_out, N);
}

// round 10
// speedup vs baseline: 1.2340x; 1.1201x over previous
#include <cuda_runtime.h>
#include <math.h>

#define NMAX 100000
#define ACC_W 16   // [coeff, edge_sca*coeff (6), edge_vec*coeff (9)]
#define EPB 256    // edges per block in edge kernel

__device__ __align__(16) float g_acc[NMAX * ACC_W];   // zero-initialized at load

// ---------------------------------------------------------------------------
// Edge phase (unchanged): staged coalesced loads + red.v4
// ---------------------------------------------------------------------------
__device__ __forceinline__ void red_v4(float* p, float a, float b, float c, float d) {
    asm volatile("red.global.add.v4.f32 [%0], {%1,%2,%3,%4};"
                 :: "l"(p), "f"(a), "f"(b), "f"(c), "f"(d) : "memory");
}

__global__ void __launch_bounds__(EPB)
edge_kernel(const float* __restrict__ edge_sca,
            const float* __restrict__ edge_vec,
            const float* __restrict__ gds,
            const int*   __restrict__ src_idx,
            int E) {
    __shared__ float s_sca[EPB * 6];
    __shared__ float s_vec[EPB * 9];

    int blockStart = blockIdx.x * EPB;
    int tid = threadIdx.x;
    int nEdges = min(EPB, E - blockStart);

    if (nEdges == EPB) {
        const float4* g4s = (const float4*)(edge_sca + (size_t)blockStart * 6);
        float4* s4s = (float4*)s_sca;
#pragma unroll 2
        for (int i = tid; i < (EPB * 6) / 4; i += EPB)
            s4s[i] = g4s[i];
        const float4* g4v = (const float4*)(edge_vec + (size_t)blockStart * 9);
        float4* s4v = (float4*)s_vec;
#pragma unroll 3
        for (int i = tid; i < (EPB * 9) / 4; i += EPB)
            s4v[i] = g4v[i];
    } else {
        for (int i = tid; i < nEdges * 6; i += EPB)
            s_sca[i] = edge_sca[(size_t)blockStart * 6 + i];
        for (int i = tid; i < nEdges * 9; i += EPB)
            s_vec[i] = edge_vec[(size_t)blockStart * 9 + i];
    }
    __syncthreads();

    if (tid >= nEdges) return;
    int e = blockStart + tid;

    float dist = __ldg(gds + e);
    if (dist > 10.0f || dist < 0.0f) return;
    float coeff = 0.5f * (__cosf(dist * 0.31415926535f) + 1.0f);

    int src = __ldg(src_idx + e);

    float es[6];
#pragma unroll
    for (int c = 0; c < 6; c++) es[c] = s_sca[tid * 6 + c] * coeff;
    float ev[9];
#pragma unroll
    for (int c = 0; c < 9; c++) ev[c] = s_vec[tid * 9 + c] * coeff;

    float* base = g_acc + (size_t)src * ACC_W;
    red_v4(base + 0,  coeff, es[0], es[1], es[2]);
    red_v4(base + 4,  es[3], es[4], es[5], ev[0]);
    red_v4(base + 8,  ev[1], ev[2], ev[3], ev[4]);
    red_v4(base + 12, ev[5], ev[6], ev[7], ev[8]);
}

// ---------------------------------------------------------------------------
// Node phase: R7 structure, but TWO nodes per thread (nd and nd+32) so every
// weight float4 in phases 2-6 is loaded once and used for both nodes.
// ---------------------------------------------------------------------------
#define O_NSS   0      // 4x16
#define O_BNSS  64     // 16
#define O_ESS   80     // 6x16
#define O_BESS  176    // 16
#define O_NSV   192    // 4x16
#define O_BNSV  256    // 16
#define O_ESV   272    // 6x16
#define O_BESV  368    // 16
#define O_NVV   384    // 3x16
#define O_EVV   432    // 3x16
#define O_LV    480    // 16x16
#define O_LV2   736    // 16x16
#define O_LS    992    // 32x16
#define O_GATE  1504   // 16x16
#define O_BGATE 1760   // 16
#define O_DIR   1776   // 16x16
#define SW_TOT  2032

#define NPB 64         // nodes per block
#define TPB 128        // threads (4 lanes x 32 node-pairs)
#define HALF_ND 32
#define BUF_W 68       // 64 payload + 4 pad floats

__global__ void __launch_bounds__(TPB)
node_kernel(const float* __restrict__ node_sca,
            const float* __restrict__ node_vec,
            const float* __restrict__ W_nss, const float* __restrict__ b_nss,
            const float* __restrict__ W_ess, const float* __restrict__ b_ess,
            const float* __restrict__ W_nsv, const float* __restrict__ b_nsv,
            const float* __restrict__ W_esv, const float* __restrict__ b_esv,
            const float* __restrict__ W_nvv, const float* __restrict__ W_evv,
            const float* __restrict__ W_lv,  const float* __restrict__ W_lv2,
            const float* __restrict__ W_ls,  const float* __restrict__ W_gate,
            const float* __restrict__ b_gate,const float* __restrict__ W_dir,
            float* __restrict__ out, int N) {
    __shared__ __align__(16) float sW[SW_TOT];
    __shared__ float s_nv[NPB * 9];
    __shared__ __align__(16) float bufA[NPB][BUF_W];  // aggr -> osca -> ovec
    __shared__ __align__(16) float bufB[NPB][BUF_W];  // v_inter + v_norm

    int tid = threadIdx.x;
    int ndA = tid >> 2;          // 0..31
    int ndB = ndA + HALF_ND;     // 32..63
    int j   = tid & 3;
    int o0  = j * 4;
    int blockStart = blockIdx.x * NPB;
    int nNodes = min(NPB, N - blockStart);
    int nA = blockStart + ndA;
    int nB = blockStart + ndB;
    bool actA = (ndA < nNodes);
    bool actB = (ndB < nNodes);

    {   // weights -> shared (R7 style)
        const float* srcs[16] = {W_nss, b_nss, W_ess, b_ess, W_nsv, b_nsv,
                                 W_esv, b_esv, W_nvv, W_evv, W_lv, W_lv2,
                                 W_ls, W_gate, b_gate, W_dir};
        const int offs[17] = {O_NSS, O_BNSS, O_ESS, O_BESS, O_NSV, O_BNSV,
                              O_ESV, O_BESV, O_NVV, O_EVV, O_LV, O_LV2,
                              O_LS, O_GATE, O_BGATE, O_DIR, SW_TOT};
        for (int a = 0; a < 16; a++) {
            int cnt = offs[a + 1] - offs[a];
            for (int i = tid; i < cnt; i += TPB)
                sW[offs[a] + i] = srcs[a][i];
        }
    }
    {   // node_vec -> shared (coalesced)
        for (int i = tid; i < nNodes * 9; i += TPB)
            s_nv[i] = node_vec[(size_t)blockStart * 9 + i];
    }
    __syncthreads();

    // ---- Phase 1 per node (inputs transient) ----
#pragma unroll
    for (int half = 0; half < 2; half++) {
        int nd = half ? ndB : ndA;
        int n  = half ? nB  : nA;
        bool act = half ? actB : actA;
        if (!act) continue;

        float4 ns4 = ((const float4*)node_sca)[n];
        float ns[4] = {ns4.x, ns4.y, ns4.z, ns4.w};
        float nv[9];
#pragma unroll
        for (int i = 0; i < 9; i++) nv[i] = s_nv[nd * 9 + i];
        float accv[16];
        {
            float4* a4 = (float4*)(g_acc + (size_t)n * ACC_W);
#pragma unroll
            for (int q = 0; q < 4; q++) {
                float4 v = a4[q];
                accv[q * 4 + 0] = v.x; accv[q * 4 + 1] = v.y;
                accv[q * 4 + 2] = v.z; accv[q * 4 + 3] = v.w;
            }
            a4[j] = make_float4(0.f, 0.f, 0.f, 0.f);   // reset quarter j
        }
        float Cs = accv[0];
        float* Es = accv + 1;
        float* Ev = accv + 7;

#pragma unroll
        for (int cc = 0; cc < 4; cc++) {
            int c = o0 + cc;
            float nss = sW[O_BNSS + c];
            float nsv = sW[O_BNSV + c];
#pragma unroll
            for (int k = 0; k < 4; k++) {
                nss += ns[k] * sW[O_NSS + k * 16 + c];
                nsv += ns[k] * sW[O_NSV + k * 16 + c];
            }
            float ess = sW[O_BESS + c] * Cs;
            float esv = sW[O_BESV + c] * Cs;
#pragma unroll
            for (int k = 0; k < 6; k++) {
                ess += Es[k] * sW[O_ESS + k * 16 + c];
                esv += Es[k] * sW[O_ESV + k * 16 + c];
            }
            float av[3];
#pragma unroll
            for (int i = 0; i < 3; i++) {
                float nvv = 0.f, evv = 0.f;
#pragma unroll
                for (int k = 0; k < 3; k++) {
                    nvv += nv[k * 3 + i] * sW[O_NVV + k * 16 + c];
                    evv += Ev[k * 3 + i] * sW[O_EVV + k * 16 + c];
                }
                av[i] = nvv * esv + nsv * evv;
            }
            *(float4*)&bufA[nd][c * 4] = make_float4(av[0], av[1], av[2], nss * ess);
        }
    }
    __syncwarp();

    // ---- Phase 2: lv + ls-scalar-half, both nodes share weight loads ----
    float viA[4][3], viB[4][3], oscaA[4], oscaB[4];
#pragma unroll
    for (int oo = 0; oo < 4; oo++) {
        viA[oo][0] = viA[oo][1] = viA[oo][2] = 0.f;
        viB[oo][0] = viB[oo][1] = viB[oo][2] = 0.f;
        oscaA[oo] = oscaB[oo] = 0.f;
    }
#pragma unroll
    for (int c = 0; c < 16; c++) {
        float4 wlv = *(const float4*)&sW[O_LV + c * 16 + o0];
        float4 wls = *(const float4*)&sW[O_LS + (c + 16) * 16 + o0];
        float4 a = *(const float4*)&bufA[ndA][c * 4];
        float4 b = *(const float4*)&bufA[ndB][c * 4];
        viA[0][0] += a.x * wlv.x; viA[0][1] += a.y * wlv.x; viA[0][2] += a.z * wlv.x;
        viA[1][0] += a.x * wlv.y; viA[1][1] += a.y * wlv.y; viA[1][2] += a.z * wlv.y;
        viA[2][0] += a.x * wlv.z; viA[2][1] += a.y * wlv.z; viA[2][2] += a.z * wlv.z;
        viA[3][0] += a.x * wlv.w; viA[3][1] += a.y * wlv.w; viA[3][2] += a.z * wlv.w;
        oscaA[0] += a.w * wls.x; oscaA[1] += a.w * wls.y;
        oscaA[2] += a.w * wls.z; oscaA[3] += a.w * wls.w;
        viB[0][0] += b.x * wlv.x; viB[0][1] += b.y * wlv.x; viB[0][2] += b.z * wlv.x;
        viB[1][0] += b.x * wlv.y; viB[1][1] += b.y * wlv.y; viB[1][2] += b.z * wlv.y;
        viB[2][0] += b.x * wlv.z; viB[2][1] += b.y * wlv.z; viB[2][2] += b.z * wlv.z;
        viB[3][0] += b.x * wlv.w; viB[3][1] += b.y * wlv.w; viB[3][2] += b.z * wlv.w;
        oscaB[0] += b.w * wls.x; oscaB[1] += b.w * wls.y;
        oscaB[2] += b.w * wls.z; oscaB[3] += b.w * wls.w;
    }
#pragma unroll
    for (int oo = 0; oo < 4; oo++) {
        float vnA = sqrtf(viA[oo][0] * viA[oo][0] + viA[oo][1] * viA[oo][1] +
                          viA[oo][2] * viA[oo][2]);
        *(float4*)&bufB[ndA][(o0 + oo) * 4] =
            make_float4(viA[oo][0], viA[oo][1], viA[oo][2], vnA);
        float vnB = sqrtf(viB[oo][0] * viB[oo][0] + viB[oo][1] * viB[oo][1] +
                          viB[oo][2] * viB[oo][2]);
        *(float4*)&bufB[ndB][(o0 + oo) * 4] =
            make_float4(viB[oo][0], viB[oo][1], viB[oo][2], vnB);
    }
    __syncwarp();

    // ---- Phase 3: osca v_norm-half; publish osca ----
#pragma unroll
    for (int c = 0; c < 16; c++) {
        float4 wls = *(const float4*)&sW[O_LS + c * 16 + o0];
        float vnA = bufB[ndA][c * 4 + 3];
        float vnB = bufB[ndB][c * 4 + 3];
        oscaA[0] += vnA * wls.x; oscaA[1] += vnA * wls.y;
        oscaA[2] += vnA * wls.z; oscaA[3] += vnA * wls.w;
        oscaB[0] += vnB * wls.x; oscaB[1] += vnB * wls.y;
        oscaB[2] += vnB * wls.z; oscaB[3] += vnB * wls.w;
    }
    *(float4*)&bufA[ndA][o0] = make_float4(oscaA[0], oscaA[1], oscaA[2], oscaA[3]);
    *(float4*)&bufA[ndB][o0] = make_float4(oscaB[0], oscaB[1], oscaB[2], oscaB[3]);
    __syncwarp();

    // ---- Phase 4: gate ----
    float gateA[4], gateB[4];
#pragma unroll
    for (int oo = 0; oo < 4; oo++) gateA[oo] = gateB[oo] = sW[O_BGATE + o0 + oo];
#pragma unroll
    for (int c4 = 0; c4 < 4; c4++) {
        float4 ocA = *(const float4*)&bufA[ndA][c4 * 4];
        float4 ocB = *(const float4*)&bufA[ndB][c4 * 4];
        float av[4] = {ocA.x, ocA.y, ocA.z, ocA.w};
        float bv[4] = {ocB.x, ocB.y, ocB.z, ocB.w};
#pragma unroll
        for (int q = 0; q < 4; q++) {
            float4 wg = *(const float4*)&sW[O_GATE + (c4 * 4 + q) * 16 + o0];
            gateA[0] += av[q] * wg.x; gateA[1] += av[q] * wg.y;
            gateA[2] += av[q] * wg.z; gateA[3] += av[q] * wg.w;
            gateB[0] += bv[q] * wg.x; gateB[1] += bv[q] * wg.y;
            gateB[2] += bv[q] * wg.z; gateB[3] += bv[q] * wg.w;
        }
    }
#pragma unroll
    for (int oo = 0; oo < 4; oo++) {
        gateA[oo] = 1.0f / (1.0f + __expf(-gateA[oo]));
        gateB[oo] = 1.0f / (1.0f + __expf(-gateB[oo]));
    }
    __syncwarp();   // osca reads done; bufA reusable for ovec

    // ---- Phase 5: lv2 -> ovec (gated); publish ----
    float ovA[4][3], ovB[4][3];
#pragma unroll
    for (int oo = 0; oo < 4; oo++) {
        ovA[oo][0] = ovA[oo][1] = ovA[oo][2] = 0.f;
        ovB[oo][0] = ovB[oo][1] = ovB[oo][2] = 0.f;
    }
#pragma unroll
    for (int c = 0; c < 16; c++) {
        float4 w = *(const float4*)&sW[O_LV2 + c * 16 + o0];
        float4 vA = *(const float4*)&bufB[ndA][c * 4];
        float4 vB = *(const float4*)&bufB[ndB][c * 4];
        ovA[0][0] += vA.x * w.x; ovA[0][1] += vA.y * w.x; ovA[0][2] += vA.z * w.x;
        ovA[1][0] += vA.x * w.y; ovA[1][1] += vA.y * w.y; ovA[1][2] += vA.z * w.y;
        ovA[2][0] += vA.x * w.z; ovA[2][1] += vA.y * w.z; ovA[2][2] += vA.z * w.z;
        ovA[3][0] += vA.x * w.w; ovA[3][1] += vA.y * w.w; ovA[3][2] += vA.z * w.w;
        ovB[0][0] += vB.x * w.x; ovB[0][1] += vB.y * w.x; ovB[0][2] += vB.z * w.x;
        ovB[1][0] += vB.x * w.y; ovB[1][1] += vB.y * w.y; ovB[1][2] += vB.z * w.y;
        ovB[2][0] += vB.x * w.z; ovB[2][1] += vB.y * w.z; ovB[2][2] += vB.z * w.z;
        ovB[3][0] += vB.x * w.w; ovB[3][1] += vB.y * w.w; ovB[3][2] += vB.z * w.w;
    }
#pragma unroll
    for (int oo = 0; oo < 4; oo++) {
        ovA[oo][0] *= gateA[oo]; ovA[oo][1] *= gateA[oo]; ovA[oo][2] *= gateA[oo];
        ovB[oo][0] *= gateB[oo]; ovB[oo][1] *= gateB[oo]; ovB[oo][2] *= gateB[oo];
        *(float4*)&bufA[ndA][(o0 + oo) * 4] =
            make_float4(ovA[oo][0], ovA[oo][1], ovA[oo][2], 0.f);
        *(float4*)&bufA[ndB][(o0 + oo) * 4] =
            make_float4(ovB[oo][0], ovB[oo][1], ovB[oo][2], 0.f);
    }
    __syncwarp();

    // ---- Phase 6: direction + VNLeakyReLU + writes ----
    float dA[4][3], dB[4][3];
#pragma unroll
    for (int oo = 0; oo < 4; oo++) {
        dA[oo][0] = dA[oo][1] = dA[oo][2] = 0.f;
        dB[oo][0] = dB[oo][1] = dB[oo][2] = 0.f;
    }
#pragma unroll
    for (int c = 0; c < 16; c++) {
        float4 w = *(const float4*)&sW[O_DIR + c * 16 + o0];
        float4 vA = *(const float4*)&bufA[ndA][c * 4];
        float4 vB = *(const float4*)&bufA[ndB][c * 4];
        dA[0][0] += vA.x * w.x; dA[0][1] += vA.y * w.x; dA[0][2] += vA.z * w.x;
        dA[1][0] += vA.x * w.y; dA[1][1] += vA.y * w.y; dA[1][2] += vA.z * w.y;
        dA[2][0] += vA.x * w.z; dA[2][1] += vA.y * w.z; dA[2][2] += vA.z * w.z;
        dA[3][0] += vA.x * w.w; dA[3][1] += vA.y * w.w; dA[3][2] += vA.z * w.w;
        dB[0][0] += vB.x * w.x; dB[0][1] += vB.y * w.x; dB[0][2] += vB.z * w.x;
        dB[1][0] += vB.x * w.y; dB[1][1] += vB.y * w.y; dB[1][2] += vB.z * w.y;
        dB[2][0] += vB.x * w.z; dB[2][1] += vB.y * w.z; dB[2][2] += vB.z * w.z;
        dB[3][0] += vB.x * w.w; dB[3][1] += vB.y * w.w; dB[3][2] += vB.z * w.w;
    }

    float* out_vec = out + (size_t)N * 16;
#pragma unroll
    for (int half = 0; half < 2; half++) {
        bool act = half ? actB : actA;
        if (!act) continue;
        int n = half ? nB : nA;
        float (*ov)[3] = half ? ovB : ovA;
        float (*d)[3]  = half ? dB  : dA;
        float* osca    = half ? oscaB : oscaA;

        float res[12];
#pragma unroll
        for (int oo = 0; oo < 4; oo++) {
            float v0 = ov[oo][0], v1 = ov[oo][1], v2 = ov[oo][2];
            float d0 = d[oo][0], d1 = d[oo][1], d2 = d[oo][2];
            float dot = v0 * d0 + v1 * d1 + v2 * d2;
            float r0 = v0, r1 = v1, r2 = v2;
            if (dot < 0.0f) {
                float k = 0.8f * dot / (d0 * d0 + d1 * d1 + d2 * d2 + 1e-6f);
                r0 = v0 - k * d0; r1 = v1 - k * d1; r2 = v2 - k * d2;
            }
            res[oo * 3 + 0] = r0; res[oo * 3 + 1] = r1; res[oo * 3 + 2] = r2;
        }
        float4* dv = (float4*)(out_vec + (size_t)n * 48 + j * 12);
#pragma unroll
        for (int q = 0; q < 3; q++)
            dv[q] = make_float4(res[q * 4 + 0], res[q * 4 + 1],
                                res[q * 4 + 2], res[q * 4 + 3]);

        float s0 = osca[0], s1 = osca[1], s2 = osca[2], s3 = osca[3];
        s0 = (s0 >= 0.f) ? s0 : 0.01f * s0;
        s1 = (s1 >= 0.f) ? s1 : 0.01f * s1;
        s2 = (s2 >= 0.f) ? s2 : 0.01f * s2;
        s3 = (s3 >= 0.f) ? s3 : 0.01f * s3;
        ((float4*)(out + (size_t)n * 16 + o0))[0] = make_float4(s0, s1, s2, s3);
    }
}

// ---------------------------------------------------------------------------
extern "C" void kernel_launch(void* const* d_in, const int* in_sizes, int n_in,
                              void* d_out, int out_size) {
    const float* node_sca = (const float*)d_in[0];
    const float* node_vec = (const float*)d_in[1];
    const float* edge_sca = (const float*)d_in[2];
    const float* edge_vec = (const float*)d_in[3];
    const float* gds      = (const float*)d_in[4];
    const int*   ei       = (const int*)d_in[5];   // [2,E]; row 0 = src
    const float* W_nss  = (const float*)d_in[6];
    const float* b_nss  = (const float*)d_in[7];
    const float* W_ess  = (const float*)d_in[8];
    const float* b_ess  = (const float*)d_in[9];
    const float* W_nsv  = (const float*)d_in[10];
    const float* b_nsv  = (const float*)d_in[11];
    const float* W_esv  = (const float*)d_in[12];
    const float* b_esv  = (const float*)d_in[13];
    const float* W_nvv  = (const float*)d_in[14];
    const float* W_evv  = (const float*)d_in[15];
    const float* W_lv   = (const float*)d_in[16];
    const float* W_lv2  = (const float*)d_in[17];
    const float* W_ls   = (const float*)d_in[18];
    const float* W_gate = (const float*)d_in[19];
    const float* b_gate = (const float*)d_in[20];
    const float* W_dir  = (const float*)d_in[21];

    int N = in_sizes[0] / 4;
    int E = in_sizes[4];

    int eblocks = (E + EPB - 1) / EPB;
    edge_kernel<<<eblocks, EPB>>>(edge_sca, edge_vec, gds, ei, E);

    int nblocks = (N + NPB - 1) / NPB;
    node_kernel<<<nblocks, TPB>>>(node_sca, node_vec,
                                  W_nss, b_nss, W_ess, b_ess,
                                  W_nsv, b_nsv, W_esv, b_esv,
                                  W_nvv, W_evv, W_lv, W_lv2,
                                  W_ls, W_gate, b_gate, W_dir,
                                  (float*)d_out, N);
}